// round 14
// baseline (speedup 1.0000x reference)
#include <cuda_runtime.h>
#include <cuda_fp16.h>
#include <math.h>
#include <stdint.h>

// Problem constants (fixed by the dataset).
constexpr int NN = 10000;          // nodes
constexpr int DD = 512;            // feature dim = H*C
constexpr int EE = 160000;         // edges
constexpr int ET = EE + NN;        // edges + self loops
constexpr int MPAD = 10112;        // 79 * 128
constexpr int ROWB = DD * 2;       // bytes per fp16 feature row (1024)

// Scratch (no cudaMalloc allowed) ------------------------------------------
__device__ __half g_XLh[MPAD * DD];        // x @ W_l (fp16, gathered by aggregate)
__device__ __half g_XRh[MPAD * DD];        // x @ W_r (fp16, logit-only consumer)
__device__ __half g_xh[MPAD * DD];         // fp16 copy of x (GEMM A operand)
__device__ __half g_wt[2 * DD * DD];       // W^T (K-major [n][k]) fp16, {W_l, W_r}
__device__ int g_counts[NN];               // static-zero; scatter re-zeroes each run
__device__ int g_rowptr[NN + 1];
__device__ int g_cursor[NN];
__device__ int g_srcb[ET];                 // CSR source BYTE offsets (src * ROWB)

// ---------------------------------------------------------------------------
// helpers
// ---------------------------------------------------------------------------
__device__ __forceinline__ uint32_t smem_u32(const void* p) {
    uint32_t a;
    asm("{ .reg .u64 t; cvta.to.shared.u64 t, %1; cvt.u32.u64 %0, t; }" : "=r"(a) : "l"(p));
    return a;
}
__device__ __forceinline__ void cp_async16(uint32_t sdst, const void* gsrc) {
    asm volatile("cp.async.cg.shared.global [%0], [%1], 16;"
                 :: "r"(sdst), "l"(__cvta_generic_to_global(gsrc)) : "memory");
}
__device__ __forceinline__ void cp_commit() {
    asm volatile("cp.async.commit_group;" ::: "memory");
}
template <int N>
__device__ __forceinline__ void cp_wait() {
    asm volatile("cp.async.wait_group %0;" :: "n"(N) : "memory");
}
__device__ __forceinline__ void ldm_x4(uint32_t& r0, uint32_t& r1, uint32_t& r2, uint32_t& r3,
                                       uint32_t addr) {
    asm volatile("ldmatrix.sync.aligned.m8n8.x4.shared.b16 {%0,%1,%2,%3}, [%4];"
                 : "=r"(r0), "=r"(r1), "=r"(r2), "=r"(r3) : "r"(addr));
}
__device__ __forceinline__ void mma_f16(float* c, const uint32_t* a, const uint32_t* b) {
    asm volatile(
        "mma.sync.aligned.m16n8k16.row.col.f32.f16.f16.f32 "
        "{%0,%1,%2,%3}, {%4,%5,%6,%7}, {%8,%9}, {%0,%1,%2,%3};"
        : "+f"(c[0]), "+f"(c[1]), "+f"(c[2]), "+f"(c[3])
        : "r"(a[0]), "r"(a[1]), "r"(a[2]), "r"(a[3]), "r"(b[0]), "r"(b[1]));
}

// ---------------------------------------------------------------------------
// Fused prep: conv_x (blocks [0, NB_CX)), conv_w (next 512), count (next 665).
// ---------------------------------------------------------------------------
constexpr int NB_CX = MPAD * DD / 4 / 256;        // 5056
constexpr int NB_CW = 512;                        // 16 x 16 x 2
constexpr int NB_CNT = (ET + 255) / 256;          // 665
constexpr int NB_PREP = NB_CX + NB_CW + NB_CNT;

__global__ __launch_bounds__(256) void prep_kernel(const float* __restrict__ x,
                                                   const float* __restrict__ Wl,
                                                   const float* __restrict__ Wr,
                                                   const int* __restrict__ ei) {
    __shared__ float tile[32][33];
    const int bx = blockIdx.x;
    const int tid = threadIdx.x;

    if (bx < NB_CX) {
        // ---- conv_x: x -> fp16 (rows >= NN zero-padded), one float4/thread
        const int e = (bx * 256 + tid) * 4;
        const int row = e >> 9;
        float4 v = make_float4(0.f, 0.f, 0.f, 0.f);
        if (row < NN) v = *(const float4*)(x + e);
        ((__half2*)(g_xh + e))[0] = __floats2half2_rn(v.x, v.y);
        ((__half2*)(g_xh + e))[1] = __floats2half2_rn(v.z, v.w);
    } else if (bx < NB_CX + NB_CW) {
        // ---- conv_w: transpose W ([k][n] -> [n][k]) to fp16
        const int w = bx - NB_CX;
        const int z = w >> 8;
        const int rem = w & 255;
        const int n0 = (rem & 15) * 32;
        const int k0 = (rem >> 4) * 32;
        const int tx = tid & 31, ty = tid >> 5;
        const float* W = z ? Wr : Wl;
#pragma unroll
        for (int r = 0; r < 4; r++) {
            int k = k0 + ty + r * 8;
            tile[ty + r * 8][tx] = W[(size_t)k * DD + n0 + tx];
        }
        __syncthreads();
        const size_t base = (size_t)z * DD * DD;
#pragma unroll
        for (int r = 0; r < 4; r++) {
            int n = n0 + ty + r * 8;
            g_wt[base + (size_t)n * DD + k0 + tx] = __float2half_rn(tile[tx][ty + r * 8]);
        }
    } else {
        // ---- count: histogram of dst (self loops appended)
        const int e = (bx - NB_CX - NB_CW) * 256 + tid;
        if (e < ET) {
            int d = (e < EE) ? ei[EE + e] : (e - EE);
            atomicAdd(&g_counts[d], 1);
        }
    }
}

// ---------------------------------------------------------------------------
// single-pass scan: 1024 threads x 10 items
// ---------------------------------------------------------------------------
__global__ __launch_bounds__(1024) void scan_kernel() {
    __shared__ int wsum[32];
    const int tid = threadIdx.x;
    const int lane = tid & 31;
    const int wid = tid >> 5;
    const int base = tid * 10;
    int v[10];
    int s = 0;
#pragma unroll
    for (int i = 0; i < 10; i++) {
        const int idx = base + i;
        v[i] = (idx < NN) ? g_counts[idx] : 0;
        s += v[i];
    }
    int x = s;
#pragma unroll
    for (int o = 1; o < 32; o <<= 1) {
        int y = __shfl_up_sync(0xffffffffu, x, o);
        if (lane >= o) x += y;
    }
    if (lane == 31) wsum[wid] = x;
    __syncthreads();
    if (wid == 0) {
        int t = wsum[lane];
#pragma unroll
        for (int o = 1; o < 32; o <<= 1) {
            int y = __shfl_up_sync(0xffffffffu, t, o);
            if (lane >= o) t += y;
        }
        wsum[lane] = t;
    }
    __syncthreads();
    int run = (wid ? wsum[wid - 1] : 0) + x - s;
#pragma unroll
    for (int i = 0; i < 10; i++) {
        const int idx = base + i;
        if (idx < NN) {
            g_rowptr[idx] = run;
            g_cursor[idx] = run;
        }
        run += v[i];
    }
    if (tid == 1023) g_rowptr[NN] = run;
}

// ---------------------------------------------------------------------------
// Fused GEMM + scatter, 512 threads/CTA, BN=128.
// GEMM blocks [0, NB_GEMM): BM=128, BN=128, BK=16, 16 warps (4m x 4n),
// warp tile 32x32 per z. A re-read 4x instead of 8x (-25% L2 traffic).
// Scatter blocks after (512 threads each).
// ---------------------------------------------------------------------------
constexpr int BM = 128, BN = 128, BK = 16;
constexpr int PITCH = 48;                   // bytes per smem row (32B data + 16B pad)
constexpr int SZ_A = BM * PITCH;            // 6144
constexpr int SZ_B = BN * PITCH;            // 6144 (per z)
constexpr int OFF_A = 0;
constexpr int OFF_B0 = SZ_A;
constexpr int OFF_B1 = SZ_A + SZ_B;
constexpr int STAGE = SZ_A + 2 * SZ_B;      // 18432
constexpr int GN = DD / BN;                 // 4
constexpr int NB_GEMM = GN * (MPAD / BM);   // 316
constexpr int NB_SCT = (ET + 511) / 512;    // 333
constexpr int NB_GS = NB_GEMM + NB_SCT;

__global__ __launch_bounds__(512, 1) void gemm_scatter_kernel(const int* __restrict__ ei) {
    const int bx = blockIdx.x;
    const int tid = threadIdx.x;

    if (bx >= NB_GEMM) {
        // ---- scatter (CSR fill, byte offsets) + counts re-zero
        const int e = (bx - NB_GEMM) * 512 + tid;
        if (e < ET) {
            if (e < NN) g_counts[e] = 0;   // restore zero-invariant for next run
            int d, s;
            if (e < EE) { s = ei[e]; d = ei[EE + e]; }
            else        { s = e - EE; d = e - EE; }
            int pos = atomicAdd(&g_cursor[d], 1);
            g_srcb[pos] = s * ROWB;        // pre-multiplied byte offset
        }
        return;
    }

    // ---- GEMM
    extern __shared__ char smem[];
    const uint32_t sbase = smem_u32(smem);
    const int wid = tid >> 5;               // 0..15
    const int lane = tid & 31;
    const int warp_m = (wid & 3) * 32;      // 0,32,64,96
    const int warp_n = (wid >> 2) * 32;     // 0,32,64,96

    const int brow = (bx / GN) * BM;
    const int bn = (bx % GN) * BN;

    // cp.async mappings (16B chunks; each row of BK=16 halves = 32B = 2 chunks)
    // A: threads 0..255 (128 rows x 2 chunks). B: all 512 threads
    // (z = tid>>8, 128 rows x 2 chunks per z).
    const int a_row = (tid & 255) >> 1;     // 0..127
    const int a_c = (tid & 1);
    const int b_z = tid >> 8;               // 0/1 weight select
    const __half* Bsrc = g_wt + (size_t)b_z * DD * DD;
    const uint32_t b_dst_off = b_z ? OFF_B1 : OFF_B0;

    auto load_stage = [&](int kc, int s) {
        const uint32_t st = sbase + s * STAGE;
        if (tid < 256) {
            const size_t ga = (size_t)(brow + a_row) * DD + kc * BK + a_c * 8;
            cp_async16(st + OFF_A + a_row * PITCH + a_c * 16, g_xh + ga);
        }
        const size_t gb = (size_t)(bn + a_row) * DD + kc * BK + a_c * 8;
        cp_async16(st + b_dst_off + a_row * PITCH + a_c * 16, Bsrc + gb);
        cp_commit();
    };

    float acc[2][2][4][4];                  // [z][m][n][q]
#pragma unroll
    for (int z = 0; z < 2; z++)
#pragma unroll
        for (int m = 0; m < 2; m++)
#pragma unroll
            for (int n = 0; n < 4; n++)
#pragma unroll
                for (int q = 0; q < 4; q++) acc[z][m][n][q] = 0.f;

    const int ar = lane & 15, ah = lane >> 4;               // A: row, k-half
    const int bi = lane & 7, bs = lane >> 3;                // B: row-in-8, selector
    const uint32_t a_off = (uint32_t)((warp_m + ar) * PITCH + ah * 16);
    const uint32_t b_off = (uint32_t)((warp_n + (bs >> 1) * 8 + bi) * PITCH + (bs & 1) * 16);

    constexpr int NKC = DD / BK;            // 32
    load_stage(0, 0);

    for (int kc = 0; kc < NKC; kc++) {
        if (kc + 1 < NKC) {
            load_stage(kc + 1, (kc + 1) & 1);
            cp_wait<1>();
        } else {
            cp_wait<0>();
        }
        __syncthreads();

        const uint32_t st = sbase + (kc & 1) * STAGE;
        uint32_t am[2][4], bm[2][2][4];
#pragma unroll
        for (int m = 0; m < 2; m++)
            ldm_x4(am[m][0], am[m][1], am[m][2], am[m][3],
                   st + OFF_A + a_off + m * 16 * PITCH);
#pragma unroll
        for (int g = 0; g < 2; g++) {
            ldm_x4(bm[0][g][0], bm[0][g][1], bm[0][g][2], bm[0][g][3],
                   st + OFF_B0 + b_off + g * 16 * PITCH);
            ldm_x4(bm[1][g][0], bm[1][g][1], bm[1][g][2], bm[1][g][3],
                   st + OFF_B1 + b_off + g * 16 * PITCH);
        }
#pragma unroll
        for (int z = 0; z < 2; z++)
#pragma unroll
            for (int m = 0; m < 2; m++)
#pragma unroll
                for (int n = 0; n < 4; n++)
                    mma_f16(acc[z][m][n], am[m], &bm[z][n >> 1][(n & 1) * 2]);
        __syncthreads();
    }

    // Epilogue: z=0 -> fp16 XL, z=1 -> fp16 XR
    const int cr = lane >> 2;               // 0..7
    const int cc = (lane & 3) * 2;
#pragma unroll
    for (int m = 0; m < 2; m++) {
#pragma unroll
        for (int half = 0; half < 2; half++) {
            const int gm = brow + warp_m + m * 16 + cr + half * 8;
            if (gm < NN) {
                __half* dst0 = g_XLh + (size_t)gm * DD + bn + warp_n + cc;
                __half* dst1 = g_XRh + (size_t)gm * DD + bn + warp_n + cc;
#pragma unroll
                for (int n = 0; n < 4; n++) {
                    *(__half2*)(dst0 + n * 8) = __floats2half2_rn(
                        acc[0][m][n][half * 2], acc[0][m][n][half * 2 + 1]);
                    *(__half2*)(dst1 + n * 8) = __floats2half2_rn(
                        acc[1][m][n][half * 2], acc[1][m][n][half * 2 + 1]);
                }
            }
        }
    }
}

// ---------------------------------------------------------------------------
// Fused gather + segment-softmax + weighted aggregate + ELU + residual.
// TWO warps per dst node; 8 channels per lane (head = 8-lane group).
// Half2 logit path (LeakyReLU(s) = 0.6s + 0.4|s|, exact), direct exp,
// fp32 accumulators, pre-multiplied byte offsets, pair prefetch (MLP 4).
// ---------------------------------------------------------------------------
__global__ __launch_bounds__(256) void aggregate_kernel(const float* __restrict__ x,
                                                        const float* __restrict__ att,
                                                        const float* __restrict__ bias,
                                                        float* __restrict__ out) {
    const int gwarp = (blockIdx.x * blockDim.x + threadIdx.x) >> 5;  // 0..2*NN-1
    if (gwarp >= 2 * NN) return;
    const int gw = gwarp >> 1;                 // node
    const int lane = threadIdx.x & 31;
    const int bd = (gwarp & 1) * 256 + lane * 8;   // 8 channels; head = bd/64
    const int bdb = bd * 2;                        // byte offset within a row

    // Pre-scaled attention (half2) and xr (half2, loaded raw).
    __half2 a6[4], a4[4], xrh[4];
    {
        float4 t0 = *(const float4*)(att + bd);
        float4 t1 = *(const float4*)(att + bd + 4);
        a6[0] = __floats2half2_rn(0.6f * t0.x, 0.6f * t0.y);
        a6[1] = __floats2half2_rn(0.6f * t0.z, 0.6f * t0.w);
        a6[2] = __floats2half2_rn(0.6f * t1.x, 0.6f * t1.y);
        a6[3] = __floats2half2_rn(0.6f * t1.z, 0.6f * t1.w);
        a4[0] = __floats2half2_rn(0.4f * t0.x, 0.4f * t0.y);
        a4[1] = __floats2half2_rn(0.4f * t0.z, 0.4f * t0.w);
        a4[2] = __floats2half2_rn(0.4f * t1.x, 0.4f * t1.y);
        a4[3] = __floats2half2_rn(0.4f * t1.z, 0.4f * t1.w);
        uint4 u = *(const uint4*)((const char*)g_XRh + (size_t)gw * ROWB + bdb);
        xrh[0] = *(const __half2*)&u.x;
        xrh[1] = *(const __half2*)&u.y;
        xrh[2] = *(const __half2*)&u.z;
        xrh[3] = *(const __half2*)&u.w;
    }

    float acc[8];
#pragma unroll
    for (int t = 0; t < 8; t++) acc[t] = 0.f;
    float denom = 0.f;

    const int e0 = g_rowptr[gw];
    const int e1 = g_rowptr[gw + 1];   // e1 > e0 guaranteed (self loop)

    auto row_ptr = [&](int e) {
        return (const uint4*)((const char*)g_XLh + (size_t)(uint32_t)g_srcb[e] + bdb);
    };

    // softmax accumulation for one loaded row (1 uint4 = 4 half2 = 8 halves)
    auto process = [&](uint4 c) {
        __half2 xlh[4];
        xlh[0] = *(const __half2*)&c.x;
        xlh[1] = *(const __half2*)&c.y;
        xlh[2] = *(const __half2*)&c.z;
        xlh[3] = *(const __half2*)&c.w;

        // half2 logit: p2 += a6*(xl+xr) + a4*|xl+xr|
        __half2 p2 = __floats2half2_rn(0.f, 0.f);
#pragma unroll
        for (int q = 0; q < 4; q++) {
            __half2 s = __hadd2(xlh[q], xrh[q]);
            p2 = __hfma2(a6[q], s, p2);
            p2 = __hfma2(a4[q], __habs2(s), p2);
        }
        float2 pf = __half22float2(p2);
        float part = pf.x + pf.y;
        // reduce over the 8 lanes of this head (64 channels / 8 per lane)
        part += __shfl_xor_sync(0xffffffffu, part, 1);
        part += __shfl_xor_sync(0xffffffffu, part, 2);
        part += __shfl_xor_sync(0xffffffffu, part, 4);
        const float w = __expf(part);
        denom += w;
#pragma unroll
        for (int q = 0; q < 4; q++) {
            float2 f = __half22float2(xlh[q]);
            acc[2 * q]     = fmaf(w, f.x, acc[2 * q]);
            acc[2 * q + 1] = fmaf(w, f.y, acc[2 * q + 1]);
        }
    };

    int e = e0;
    int rem = e1 - e0;
    uint4 p0, p1;
    p0 = *row_ptr(e);
    if (rem > 1) p1 = *row_ptr(e + 1);
    while (rem >= 2) {
        const uint4 c0 = p0, c1 = p1;
        const int nx = e + 2;
        const int nrem = rem - 2;
        if (nrem > 0) {
            p0 = *row_ptr(nx);
            if (nrem > 1) p1 = *row_ptr(nx + 1);
        }
        process(c0);
        process(c1);
        e = nx;
        rem = nrem;
    }
    if (rem == 1) process(p0);

    const float inv = 1.0f / denom;
    const size_t ob = (size_t)gw * DD + bd;
#pragma unroll
    for (int q = 0; q < 2; q++) {
        float4 xv = *(const float4*)(x + ob + 4 * q);
        float r[4];
#pragma unroll
        for (int u = 0; u < 4; u++) {
            const int t = 4 * q + u;
            float v = acc[t] * inv + bias[bd + t];
            float e2 = (v > 0.f) ? v : expm1f(v);
            r[u] = e2 + ((const float*)&xv)[u];
        }
        *(float4*)(out + ob + 4 * q) = make_float4(r[0], r[1], r[2], r[3]);
    }
}

// ---------------------------------------------------------------------------
extern "C" void kernel_launch(void* const* d_in, const int* in_sizes, int n_in,
                              void* d_out, int out_size) {
    const float* x    = (const float*)d_in[0];
    const int*   ei   = (const int*)d_in[1];
    const float* W_l  = (const float*)d_in[2];
    const float* W_r  = (const float*)d_in[3];
    const float* att  = (const float*)d_in[4];
    const float* bias = (const float*)d_in[5];
    float* out = (float*)d_out;

    // 1) fused prep: x->fp16, W transpose->fp16, dst histogram
    prep_kernel<<<NB_PREP, 256>>>(x, W_l, W_r, ei);

    // 2) rowptr scan
    scan_kernel<<<1, 1024>>>();

    // 3) fused GEMM (BN=128, 512 threads) + CSR scatter
    gemm_scatter_kernel<<<NB_GS, 512, 2 * STAGE>>>(ei);

    // 4) fused softmax-aggregate + ELU + residual (2 warps per node)
    aggregate_kernel<<<(2 * NN * 32 + 255) / 256, 256>>>(x, att, bias, out);
}

// round 15
// speedup vs baseline: 1.0477x; 1.0477x over previous
#include <cuda_runtime.h>
#include <cuda_fp16.h>
#include <math.h>
#include <stdint.h>

// Problem constants (fixed by the dataset).
constexpr int NN = 10000;          // nodes
constexpr int DD = 512;            // feature dim = H*C
constexpr int EE = 160000;         // edges
constexpr int ET = EE + NN;        // edges + self loops
constexpr int MPAD = 10112;        // 79 * 128
constexpr int ROWB = DD * 2;       // bytes per fp16 feature row (1024)

// Scratch (no cudaMalloc allowed) ------------------------------------------
__device__ __half g_XLh[MPAD * DD];        // x @ W_l (fp16, gathered by aggregate)
__device__ __half g_XRh[MPAD * DD];        // x @ W_r (fp16, logit-only consumer)
__device__ __half g_xh[MPAD * DD];         // fp16 copy of x (GEMM A operand)
__device__ __half g_wt[2 * DD * DD];       // W^T (K-major [n][k]) fp16, {W_l, W_r}
__device__ int g_counts[NN];               // static-zero; scatter re-zeroes each run
__device__ int g_rowptr[NN + 1];
__device__ int g_cursor[NN];
__device__ int g_srcb[ET];                 // CSR source BYTE offsets (src * ROWB)

// ---------------------------------------------------------------------------
// helpers
// ---------------------------------------------------------------------------
__device__ __forceinline__ uint32_t smem_u32(const void* p) {
    uint32_t a;
    asm("{ .reg .u64 t; cvta.to.shared.u64 t, %1; cvt.u32.u64 %0, t; }" : "=r"(a) : "l"(p));
    return a;
}
__device__ __forceinline__ void cp_async16(uint32_t sdst, const void* gsrc) {
    asm volatile("cp.async.cg.shared.global [%0], [%1], 16;"
                 :: "r"(sdst), "l"(__cvta_generic_to_global(gsrc)) : "memory");
}
__device__ __forceinline__ void cp_commit() {
    asm volatile("cp.async.commit_group;" ::: "memory");
}
template <int N>
__device__ __forceinline__ void cp_wait() {
    asm volatile("cp.async.wait_group %0;" :: "n"(N) : "memory");
}
__device__ __forceinline__ void ldm_x4(uint32_t& r0, uint32_t& r1, uint32_t& r2, uint32_t& r3,
                                       uint32_t addr) {
    asm volatile("ldmatrix.sync.aligned.m8n8.x4.shared.b16 {%0,%1,%2,%3}, [%4];"
                 : "=r"(r0), "=r"(r1), "=r"(r2), "=r"(r3) : "r"(addr));
}
__device__ __forceinline__ void mma_f16(float* c, const uint32_t* a, const uint32_t* b) {
    asm volatile(
        "mma.sync.aligned.m16n8k16.row.col.f32.f16.f16.f32 "
        "{%0,%1,%2,%3}, {%4,%5,%6,%7}, {%8,%9}, {%0,%1,%2,%3};"
        : "+f"(c[0]), "+f"(c[1]), "+f"(c[2]), "+f"(c[3])
        : "r"(a[0]), "r"(a[1]), "r"(a[2]), "r"(a[3]), "r"(b[0]), "r"(b[1]));
}

// ---------------------------------------------------------------------------
// Fused prep: conv_x (blocks [0, NB_CX)), conv_w (next 512), count (next 665).
// ---------------------------------------------------------------------------
constexpr int NB_CX = MPAD * DD / 4 / 256;        // 5056
constexpr int NB_CW = 512;                        // 16 x 16 x 2
constexpr int NB_CNT = (ET + 255) / 256;          // 665
constexpr int NB_PREP = NB_CX + NB_CW + NB_CNT;

__global__ __launch_bounds__(256) void prep_kernel(const float* __restrict__ x,
                                                   const float* __restrict__ Wl,
                                                   const float* __restrict__ Wr,
                                                   const int* __restrict__ ei) {
    __shared__ float tile[32][33];
    const int bx = blockIdx.x;
    const int tid = threadIdx.x;

    if (bx < NB_CX) {
        // ---- conv_x: x -> fp16 (rows >= NN zero-padded), one float4/thread
        const int e = (bx * 256 + tid) * 4;
        const int row = e >> 9;
        float4 v = make_float4(0.f, 0.f, 0.f, 0.f);
        if (row < NN) v = *(const float4*)(x + e);
        ((__half2*)(g_xh + e))[0] = __floats2half2_rn(v.x, v.y);
        ((__half2*)(g_xh + e))[1] = __floats2half2_rn(v.z, v.w);
    } else if (bx < NB_CX + NB_CW) {
        // ---- conv_w: transpose W ([k][n] -> [n][k]) to fp16
        const int w = bx - NB_CX;
        const int z = w >> 8;
        const int rem = w & 255;
        const int n0 = (rem & 15) * 32;
        const int k0 = (rem >> 4) * 32;
        const int tx = tid & 31, ty = tid >> 5;
        const float* W = z ? Wr : Wl;
#pragma unroll
        for (int r = 0; r < 4; r++) {
            int k = k0 + ty + r * 8;
            tile[ty + r * 8][tx] = W[(size_t)k * DD + n0 + tx];
        }
        __syncthreads();
        const size_t base = (size_t)z * DD * DD;
#pragma unroll
        for (int r = 0; r < 4; r++) {
            int n = n0 + ty + r * 8;
            g_wt[base + (size_t)n * DD + k0 + tx] = __float2half_rn(tile[tx][ty + r * 8]);
        }
    } else {
        // ---- count: histogram of dst (self loops appended)
        const int e = (bx - NB_CX - NB_CW) * 256 + tid;
        if (e < ET) {
            int d = (e < EE) ? ei[EE + e] : (e - EE);
            atomicAdd(&g_counts[d], 1);
        }
    }
}

// ---------------------------------------------------------------------------
// single-pass scan: 1024 threads x 10 items
// ---------------------------------------------------------------------------
__global__ __launch_bounds__(1024) void scan_kernel() {
    __shared__ int wsum[32];
    const int tid = threadIdx.x;
    const int lane = tid & 31;
    const int wid = tid >> 5;
    const int base = tid * 10;
    int v[10];
    int s = 0;
#pragma unroll
    for (int i = 0; i < 10; i++) {
        const int idx = base + i;
        v[i] = (idx < NN) ? g_counts[idx] : 0;
        s += v[i];
    }
    int x = s;
#pragma unroll
    for (int o = 1; o < 32; o <<= 1) {
        int y = __shfl_up_sync(0xffffffffu, x, o);
        if (lane >= o) x += y;
    }
    if (lane == 31) wsum[wid] = x;
    __syncthreads();
    if (wid == 0) {
        int t = wsum[lane];
#pragma unroll
        for (int o = 1; o < 32; o <<= 1) {
            int y = __shfl_up_sync(0xffffffffu, t, o);
            if (lane >= o) t += y;
        }
        wsum[lane] = t;
    }
    __syncthreads();
    int run = (wid ? wsum[wid - 1] : 0) + x - s;
#pragma unroll
    for (int i = 0; i < 10; i++) {
        const int idx = base + i;
        if (idx < NN) {
            g_rowptr[idx] = run;
            g_cursor[idx] = run;
        }
        run += v[i];
    }
    if (tid == 1023) g_rowptr[NN] = run;
}

// ---------------------------------------------------------------------------
// Fused GEMM + scatter (R12 shape: BN=64, 256 threads — BN=128/512t measured
// 11us slower) with a THREE-stage cp.async pipeline for deeper latency cover.
// ---------------------------------------------------------------------------
constexpr int BM = 128, BN = 64, BK = 16;
constexpr int PITCH = 48;                   // bytes per smem row (32B data + 16B pad)
constexpr int SZ_A = BM * PITCH;            // 6144
constexpr int SZ_B = BN * PITCH;            // 3072 (per z)
constexpr int OFF_A = 0;
constexpr int OFF_B0 = SZ_A;
constexpr int OFF_B1 = SZ_A + SZ_B;
constexpr int STAGE = SZ_A + 2 * SZ_B;      // 12288
constexpr int NSTAGE = 3;                   // 36864 bytes total
constexpr int GN = DD / BN;                 // 8
constexpr int NB_GEMM = GN * (MPAD / BM);   // 632
constexpr int NB_GS = NB_GEMM + NB_CNT;     // + scatter blocks

__global__ __launch_bounds__(256) void gemm_scatter_kernel(const int* __restrict__ ei) {
    const int bx = blockIdx.x;
    const int tid = threadIdx.x;

    if (bx >= NB_GEMM) {
        // ---- scatter (CSR fill, byte offsets) + counts re-zero
        const int e = (bx - NB_GEMM) * 256 + tid;
        if (e < ET) {
            if (e < NN) g_counts[e] = 0;   // restore zero-invariant for next run
            int d, s;
            if (e < EE) { s = ei[e]; d = ei[EE + e]; }
            else        { s = e - EE; d = e - EE; }
            int pos = atomicAdd(&g_cursor[d], 1);
            g_srcb[pos] = s * ROWB;        // pre-multiplied byte offset
        }
        return;
    }

    // ---- GEMM
    extern __shared__ char smem[];
    const uint32_t sbase = smem_u32(smem);
    const int wid = tid >> 5;
    const int lane = tid & 31;
    const int warp_m = (wid & 3) * 32;      // 0,32,64,96
    const int warp_n = (wid >> 2) * 32;     // 0,32

    const int brow = (bx / GN) * BM;
    const int bn = (bx % GN) * BN;

    const int a_row = tid >> 1;             // 0..127
    const int a_c = (tid & 1);
    const int b_z = tid >> 7;               // 0/1 weight select
    const int b_row = (tid & 127) >> 1;     // 0..63
    const int b_c = (tid & 1);
    const __half* Bsrc = g_wt + (size_t)b_z * DD * DD;
    const uint32_t b_dst_off = b_z ? OFF_B1 : OFF_B0;

    auto load_stage = [&](int kc, int s) {
        const uint32_t st = sbase + s * STAGE;
        const size_t ga = (size_t)(brow + a_row) * DD + kc * BK + a_c * 8;
        cp_async16(st + OFF_A + a_row * PITCH + a_c * 16, g_xh + ga);
        const size_t gb = (size_t)(bn + b_row) * DD + kc * BK + b_c * 8;
        cp_async16(st + b_dst_off + b_row * PITCH + b_c * 16, Bsrc + gb);
        cp_commit();
    };

    float acc[2][2][4][4];                  // [z][m][n][q]
#pragma unroll
    for (int z = 0; z < 2; z++)
#pragma unroll
        for (int m = 0; m < 2; m++)
#pragma unroll
            for (int n = 0; n < 4; n++)
#pragma unroll
                for (int q = 0; q < 4; q++) acc[z][m][n][q] = 0.f;

    const int ar = lane & 15, ah = lane >> 4;               // A: row, k-half
    const int bi = lane & 7, bs = lane >> 3;                // B: row-in-8, selector
    const uint32_t a_off = (uint32_t)((warp_m + ar) * PITCH + ah * 16);
    const uint32_t b_off = (uint32_t)((warp_n + (bs >> 1) * 8 + bi) * PITCH + (bs & 1) * 16);

    constexpr int NKC = DD / BK;            // 32
    // 3-stage pipeline: stages kc and kc+1 in flight ahead of compute
    load_stage(0, 0);
    load_stage(1, 1);

    int stage = 0;                           // stage slot of iteration kc
    for (int kc = 0; kc < NKC; kc++) {
        if (kc + 2 < NKC) {
            load_stage(kc + 2, (stage + 2) % NSTAGE);
            cp_wait<2>();                    // ensure stage kc landed
        } else if (kc + 1 < NKC) {
            cp_wait<1>();
        } else {
            cp_wait<0>();
        }
        __syncthreads();

        const uint32_t st = sbase + stage * STAGE;
        uint32_t am[2][4], bm[2][2][4];
#pragma unroll
        for (int m = 0; m < 2; m++)
            ldm_x4(am[m][0], am[m][1], am[m][2], am[m][3],
                   st + OFF_A + a_off + m * 16 * PITCH);
#pragma unroll
        for (int g = 0; g < 2; g++) {
            ldm_x4(bm[0][g][0], bm[0][g][1], bm[0][g][2], bm[0][g][3],
                   st + OFF_B0 + b_off + g * 16 * PITCH);
            ldm_x4(bm[1][g][0], bm[1][g][1], bm[1][g][2], bm[1][g][3],
                   st + OFF_B1 + b_off + g * 16 * PITCH);
        }
#pragma unroll
        for (int z = 0; z < 2; z++)
#pragma unroll
            for (int m = 0; m < 2; m++)
#pragma unroll
                for (int n = 0; n < 4; n++)
                    mma_f16(acc[z][m][n], am[m], &bm[z][n >> 1][(n & 1) * 2]);
        __syncthreads();                     // protect stage slot before re-issue
        stage = (stage + 1) % NSTAGE;
    }

    // Epilogue: z=0 -> fp16 XL, z=1 -> fp16 XR
    const int cr = lane >> 2;               // 0..7
    const int cc = (lane & 3) * 2;
#pragma unroll
    for (int m = 0; m < 2; m++) {
#pragma unroll
        for (int half = 0; half < 2; half++) {
            const int gm = brow + warp_m + m * 16 + cr + half * 8;
            if (gm < NN) {
                __half* dst0 = g_XLh + (size_t)gm * DD + bn + warp_n + cc;
                __half* dst1 = g_XRh + (size_t)gm * DD + bn + warp_n + cc;
#pragma unroll
                for (int n = 0; n < 4; n++) {
                    *(__half2*)(dst0 + n * 8) = __floats2half2_rn(
                        acc[0][m][n][half * 2], acc[0][m][n][half * 2 + 1]);
                    *(__half2*)(dst1 + n * 8) = __floats2half2_rn(
                        acc[1][m][n][half * 2], acc[1][m][n][half * 2 + 1]);
                }
            }
        }
    }
}

// ---------------------------------------------------------------------------
// Fused gather + segment-softmax + weighted aggregate + ELU + residual.
// TWO warps per dst node; 8 channels per lane (head = 8-lane group).
// Half2 logit path (LeakyReLU(s) = 0.6s + 0.4|s|, exact), direct exp,
// fp32 accumulators, pre-multiplied byte offsets, pair prefetch (MLP 4).
// ---------------------------------------------------------------------------
__global__ __launch_bounds__(256) void aggregate_kernel(const float* __restrict__ x,
                                                        const float* __restrict__ att,
                                                        const float* __restrict__ bias,
                                                        float* __restrict__ out) {
    const int gwarp = (blockIdx.x * blockDim.x + threadIdx.x) >> 5;  // 0..2*NN-1
    if (gwarp >= 2 * NN) return;
    const int gw = gwarp >> 1;                 // node
    const int lane = threadIdx.x & 31;
    const int bd = (gwarp & 1) * 256 + lane * 8;   // 8 channels; head = bd/64
    const int bdb = bd * 2;                        // byte offset within a row

    // Pre-scaled attention (half2) and xr (half2, loaded raw).
    __half2 a6[4], a4[4], xrh[4];
    {
        float4 t0 = *(const float4*)(att + bd);
        float4 t1 = *(const float4*)(att + bd + 4);
        a6[0] = __floats2half2_rn(0.6f * t0.x, 0.6f * t0.y);
        a6[1] = __floats2half2_rn(0.6f * t0.z, 0.6f * t0.w);
        a6[2] = __floats2half2_rn(0.6f * t1.x, 0.6f * t1.y);
        a6[3] = __floats2half2_rn(0.6f * t1.z, 0.6f * t1.w);
        a4[0] = __floats2half2_rn(0.4f * t0.x, 0.4f * t0.y);
        a4[1] = __floats2half2_rn(0.4f * t0.z, 0.4f * t0.w);
        a4[2] = __floats2half2_rn(0.4f * t1.x, 0.4f * t1.y);
        a4[3] = __floats2half2_rn(0.4f * t1.z, 0.4f * t1.w);
        uint4 u = *(const uint4*)((const char*)g_XRh + (size_t)gw * ROWB + bdb);
        xrh[0] = *(const __half2*)&u.x;
        xrh[1] = *(const __half2*)&u.y;
        xrh[2] = *(const __half2*)&u.z;
        xrh[3] = *(const __half2*)&u.w;
    }

    float acc[8];
#pragma unroll
    for (int t = 0; t < 8; t++) acc[t] = 0.f;
    float denom = 0.f;

    const int e0 = g_rowptr[gw];
    const int e1 = g_rowptr[gw + 1];   // e1 > e0 guaranteed (self loop)

    auto row_ptr = [&](int e) {
        return (const uint4*)((const char*)g_XLh + (size_t)(uint32_t)g_srcb[e] + bdb);
    };

    // softmax accumulation for one loaded row (1 uint4 = 4 half2 = 8 halves)
    auto process = [&](uint4 c) {
        __half2 xlh[4];
        xlh[0] = *(const __half2*)&c.x;
        xlh[1] = *(const __half2*)&c.y;
        xlh[2] = *(const __half2*)&c.z;
        xlh[3] = *(const __half2*)&c.w;

        // half2 logit: p2 += a6*(xl+xr) + a4*|xl+xr|
        __half2 p2 = __floats2half2_rn(0.f, 0.f);
#pragma unroll
        for (int q = 0; q < 4; q++) {
            __half2 s = __hadd2(xlh[q], xrh[q]);
            p2 = __hfma2(a6[q], s, p2);
            p2 = __hfma2(a4[q], __habs2(s), p2);
        }
        float2 pf = __half22float2(p2);
        float part = pf.x + pf.y;
        // reduce over the 8 lanes of this head (64 channels / 8 per lane)
        part += __shfl_xor_sync(0xffffffffu, part, 1);
        part += __shfl_xor_sync(0xffffffffu, part, 2);
        part += __shfl_xor_sync(0xffffffffu, part, 4);
        const float w = __expf(part);
        denom += w;
#pragma unroll
        for (int q = 0; q < 4; q++) {
            float2 f = __half22float2(xlh[q]);
            acc[2 * q]     = fmaf(w, f.x, acc[2 * q]);
            acc[2 * q + 1] = fmaf(w, f.y, acc[2 * q + 1]);
        }
    };

    int e = e0;
    int rem = e1 - e0;
    uint4 p0, p1;
    p0 = *row_ptr(e);
    if (rem > 1) p1 = *row_ptr(e + 1);
    while (rem >= 2) {
        const uint4 c0 = p0, c1 = p1;
        const int nx = e + 2;
        const int nrem = rem - 2;
        if (nrem > 0) {
            p0 = *row_ptr(nx);
            if (nrem > 1) p1 = *row_ptr(nx + 1);
        }
        process(c0);
        process(c1);
        e = nx;
        rem = nrem;
    }
    if (rem == 1) process(p0);

    const float inv = 1.0f / denom;
    const size_t ob = (size_t)gw * DD + bd;
#pragma unroll
    for (int q = 0; q < 2; q++) {
        float4 xv = *(const float4*)(x + ob + 4 * q);
        float r[4];
#pragma unroll
        for (int u = 0; u < 4; u++) {
            const int t = 4 * q + u;
            float v = acc[t] * inv + bias[bd + t];
            float e2 = (v > 0.f) ? v : expm1f(v);
            r[u] = e2 + ((const float*)&xv)[u];
        }
        *(float4*)(out + ob + 4 * q) = make_float4(r[0], r[1], r[2], r[3]);
    }
}

// ---------------------------------------------------------------------------
extern "C" void kernel_launch(void* const* d_in, const int* in_sizes, int n_in,
                              void* d_out, int out_size) {
    const float* x    = (const float*)d_in[0];
    const int*   ei   = (const int*)d_in[1];
    const float* W_l  = (const float*)d_in[2];
    const float* W_r  = (const float*)d_in[3];
    const float* att  = (const float*)d_in[4];
    const float* bias = (const float*)d_in[5];
    float* out = (float*)d_out;

    // 1) fused prep: x->fp16, W transpose->fp16, dst histogram
    prep_kernel<<<NB_PREP, 256>>>(x, W_l, W_r, ei);

    // 2) rowptr scan
    scan_kernel<<<1, 1024>>>();

    // 3) fused GEMM (BN=64, 256 threads, 3-stage pipeline) + CSR scatter
    gemm_scatter_kernel<<<NB_GS, 256, NSTAGE * STAGE>>>(ei);

    // 4) fused softmax-aggregate + ELU + residual (2 warps per node)
    aggregate_kernel<<<(2 * NN * 32 + 255) / 256, 256>>>(x, att, bias, out);
}

// round 16
// speedup vs baseline: 1.1066x; 1.0562x over previous
#include <cuda_runtime.h>
#include <cuda_fp16.h>
#include <math.h>
#include <stdint.h>

// Problem constants (fixed by the dataset).
constexpr int NN = 10000;          // nodes
constexpr int DD = 512;            // feature dim = H*C
constexpr int EE = 160000;         // edges
constexpr int ET = EE + NN;        // edges + self loops
constexpr int MPAD = 10112;        // 79 * 128
constexpr int ROWB = DD * 2;       // bytes per fp16 feature row (1024)

// Scratch (no cudaMalloc allowed) ------------------------------------------
__device__ __half g_XLh[MPAD * DD];        // x @ W_l (fp16, gathered by aggregate)
__device__ __half g_XRh[MPAD * DD];        // x @ W_r (fp16, logit-only consumer)
__device__ __half g_xh[MPAD * DD];         // fp16 copy of x (GEMM A operand)
__device__ __half g_wt[2 * DD * DD];       // W^T (K-major [n][k]) fp16, {W_l, W_r}
__device__ int g_counts[NN];               // static-zero; scatter re-zeroes each run
__device__ int g_rowptr[NN + 1];
__device__ int g_cursor[NN];
__device__ int g_srcb[ET];                 // CSR source BYTE offsets (src * ROWB)

// ---------------------------------------------------------------------------
// helpers
// ---------------------------------------------------------------------------
__device__ __forceinline__ uint32_t smem_u32(const void* p) {
    uint32_t a;
    asm("{ .reg .u64 t; cvta.to.shared.u64 t, %1; cvt.u32.u64 %0, t; }" : "=r"(a) : "l"(p));
    return a;
}
__device__ __forceinline__ void cp_async16(uint32_t sdst, const void* gsrc) {
    asm volatile("cp.async.cg.shared.global [%0], [%1], 16;"
                 :: "r"(sdst), "l"(__cvta_generic_to_global(gsrc)) : "memory");
}
__device__ __forceinline__ void cp_commit() {
    asm volatile("cp.async.commit_group;" ::: "memory");
}
template <int N>
__device__ __forceinline__ void cp_wait() {
    asm volatile("cp.async.wait_group %0;" :: "n"(N) : "memory");
}
__device__ __forceinline__ void ldm_x4(uint32_t& r0, uint32_t& r1, uint32_t& r2, uint32_t& r3,
                                       uint32_t addr) {
    asm volatile("ldmatrix.sync.aligned.m8n8.x4.shared.b16 {%0,%1,%2,%3}, [%4];"
                 : "=r"(r0), "=r"(r1), "=r"(r2), "=r"(r3) : "r"(addr));
}
__device__ __forceinline__ void mma_f16(float* c, const uint32_t* a, const uint32_t* b) {
    asm volatile(
        "mma.sync.aligned.m16n8k16.row.col.f32.f16.f16.f32 "
        "{%0,%1,%2,%3}, {%4,%5,%6,%7}, {%8,%9}, {%0,%1,%2,%3};"
        : "+f"(c[0]), "+f"(c[1]), "+f"(c[2]), "+f"(c[3])
        : "r"(a[0]), "r"(a[1]), "r"(a[2]), "r"(a[3]), "r"(b[0]), "r"(b[1]));
}

// ---------------------------------------------------------------------------
// Fused prep: conv_x (blocks [0, NB_CX)), conv_w (next 512), count (next 665).
// ---------------------------------------------------------------------------
constexpr int NB_CX = MPAD * DD / 4 / 256;        // 5056
constexpr int NB_CW = 512;                        // 16 x 16 x 2
constexpr int NB_CNT = (ET + 255) / 256;          // 665
constexpr int NB_PREP = NB_CX + NB_CW + NB_CNT;

__global__ __launch_bounds__(256) void prep_kernel(const float* __restrict__ x,
                                                   const float* __restrict__ Wl,
                                                   const float* __restrict__ Wr,
                                                   const int* __restrict__ ei) {
    __shared__ float tile[32][33];
    const int bx = blockIdx.x;
    const int tid = threadIdx.x;

    if (bx < NB_CX) {
        // ---- conv_x: x -> fp16 (rows >= NN zero-padded), one float4/thread
        const int e = (bx * 256 + tid) * 4;
        const int row = e >> 9;
        float4 v = make_float4(0.f, 0.f, 0.f, 0.f);
        if (row < NN) v = *(const float4*)(x + e);
        ((__half2*)(g_xh + e))[0] = __floats2half2_rn(v.x, v.y);
        ((__half2*)(g_xh + e))[1] = __floats2half2_rn(v.z, v.w);
    } else if (bx < NB_CX + NB_CW) {
        // ---- conv_w: transpose W ([k][n] -> [n][k]) to fp16
        const int w = bx - NB_CX;
        const int z = w >> 8;
        const int rem = w & 255;
        const int n0 = (rem & 15) * 32;
        const int k0 = (rem >> 4) * 32;
        const int tx = tid & 31, ty = tid >> 5;
        const float* W = z ? Wr : Wl;
#pragma unroll
        for (int r = 0; r < 4; r++) {
            int k = k0 + ty + r * 8;
            tile[ty + r * 8][tx] = W[(size_t)k * DD + n0 + tx];
        }
        __syncthreads();
        const size_t base = (size_t)z * DD * DD;
#pragma unroll
        for (int r = 0; r < 4; r++) {
            int n = n0 + ty + r * 8;
            g_wt[base + (size_t)n * DD + k0 + tx] = __float2half_rn(tile[tx][ty + r * 8]);
        }
    } else {
        // ---- count: histogram of dst (self loops appended)
        const int e = (bx - NB_CX - NB_CW) * 256 + tid;
        if (e < ET) {
            int d = (e < EE) ? ei[EE + e] : (e - EE);
            atomicAdd(&g_counts[d], 1);
        }
    }
}

// ---------------------------------------------------------------------------
// single-pass scan: 1024 threads x 10 items
// ---------------------------------------------------------------------------
__global__ __launch_bounds__(1024) void scan_kernel() {
    __shared__ int wsum[32];
    const int tid = threadIdx.x;
    const int lane = tid & 31;
    const int wid = tid >> 5;
    const int base = tid * 10;
    int v[10];
    int s = 0;
#pragma unroll
    for (int i = 0; i < 10; i++) {
        const int idx = base + i;
        v[i] = (idx < NN) ? g_counts[idx] : 0;
        s += v[i];
    }
    int x = s;
#pragma unroll
    for (int o = 1; o < 32; o <<= 1) {
        int y = __shfl_up_sync(0xffffffffu, x, o);
        if (lane >= o) x += y;
    }
    if (lane == 31) wsum[wid] = x;
    __syncthreads();
    if (wid == 0) {
        int t = wsum[lane];
#pragma unroll
        for (int o = 1; o < 32; o <<= 1) {
            int y = __shfl_up_sync(0xffffffffu, t, o);
            if (lane >= o) t += y;
        }
        wsum[lane] = t;
    }
    __syncthreads();
    int run = (wid ? wsum[wid - 1] : 0) + x - s;
#pragma unroll
    for (int i = 0; i < 10; i++) {
        const int idx = base + i;
        if (idx < NN) {
            g_rowptr[idx] = run;
            g_cursor[idx] = run;
        }
        run += v[i];
    }
    if (tid == 1023) g_rowptr[NN] = run;
}

// ---------------------------------------------------------------------------
// Fused GEMM + scatter — EXACT R12 configuration (best measured: 110.1us).
// BM=128, BN=64, BK=16, 256 threads, 2-stage cp.async double buffer.
// (BN=128/512t: +11us; 3-stage: +5us — both measured regressions.)
// ---------------------------------------------------------------------------
constexpr int BM = 128, BN = 64, BK = 16;
constexpr int PITCH = 48;                   // bytes per smem row (32B data + 16B pad)
constexpr int SZ_A = BM * PITCH;            // 6144
constexpr int SZ_B = BN * PITCH;            // 3072 (per z)
constexpr int OFF_A = 0;
constexpr int OFF_B0 = SZ_A;
constexpr int OFF_B1 = SZ_A + SZ_B;
constexpr int STAGE = SZ_A + 2 * SZ_B;      // 12288
constexpr int GN = DD / BN;                 // 8
constexpr int NB_GEMM = GN * (MPAD / BM);   // 632
constexpr int NB_GS = NB_GEMM + NB_CNT;     // + scatter blocks

__global__ __launch_bounds__(256) void gemm_scatter_kernel(const int* __restrict__ ei) {
    const int bx = blockIdx.x;
    const int tid = threadIdx.x;

    if (bx >= NB_GEMM) {
        // ---- scatter (CSR fill, byte offsets) + counts re-zero
        const int e = (bx - NB_GEMM) * 256 + tid;
        if (e < ET) {
            if (e < NN) g_counts[e] = 0;   // restore zero-invariant for next run
            int d, s;
            if (e < EE) { s = ei[e]; d = ei[EE + e]; }
            else        { s = e - EE; d = e - EE; }
            int pos = atomicAdd(&g_cursor[d], 1);
            g_srcb[pos] = s * ROWB;        // pre-multiplied byte offset
        }
        return;
    }

    // ---- GEMM
    extern __shared__ char smem[];
    const uint32_t sbase = smem_u32(smem);
    const int wid = tid >> 5;
    const int lane = tid & 31;
    const int warp_m = (wid & 3) * 32;      // 0,32,64,96
    const int warp_n = (wid >> 2) * 32;     // 0,32

    const int brow = (bx / GN) * BM;
    const int bn = (bx % GN) * BN;

    const int a_row = tid >> 1;             // 0..127
    const int a_c = (tid & 1);
    const int b_z = tid >> 7;               // 0/1 weight select
    const int b_row = (tid & 127) >> 1;     // 0..63
    const int b_c = (tid & 1);
    const __half* Bsrc = g_wt + (size_t)b_z * DD * DD;
    const uint32_t b_dst_off = b_z ? OFF_B1 : OFF_B0;

    auto load_stage = [&](int kc, int s) {
        const uint32_t st = sbase + s * STAGE;
        const size_t ga = (size_t)(brow + a_row) * DD + kc * BK + a_c * 8;
        cp_async16(st + OFF_A + a_row * PITCH + a_c * 16, g_xh + ga);
        const size_t gb = (size_t)(bn + b_row) * DD + kc * BK + b_c * 8;
        cp_async16(st + b_dst_off + b_row * PITCH + b_c * 16, Bsrc + gb);
        cp_commit();
    };

    float acc[2][2][4][4];                  // [z][m][n][q]
#pragma unroll
    for (int z = 0; z < 2; z++)
#pragma unroll
        for (int m = 0; m < 2; m++)
#pragma unroll
            for (int n = 0; n < 4; n++)
#pragma unroll
                for (int q = 0; q < 4; q++) acc[z][m][n][q] = 0.f;

    const int ar = lane & 15, ah = lane >> 4;               // A: row, k-half
    const int bi = lane & 7, bs = lane >> 3;                // B: row-in-8, selector
    const uint32_t a_off = (uint32_t)((warp_m + ar) * PITCH + ah * 16);
    const uint32_t b_off = (uint32_t)((warp_n + (bs >> 1) * 8 + bi) * PITCH + (bs & 1) * 16);

    constexpr int NKC = DD / BK;            // 32
    load_stage(0, 0);

    for (int kc = 0; kc < NKC; kc++) {
        if (kc + 1 < NKC) {
            load_stage(kc + 1, (kc + 1) & 1);
            cp_wait<1>();
        } else {
            cp_wait<0>();
        }
        __syncthreads();

        const uint32_t st = sbase + (kc & 1) * STAGE;
        uint32_t am[2][4], bm[2][2][4];
#pragma unroll
        for (int m = 0; m < 2; m++)
            ldm_x4(am[m][0], am[m][1], am[m][2], am[m][3],
                   st + OFF_A + a_off + m * 16 * PITCH);
#pragma unroll
        for (int g = 0; g < 2; g++) {
            ldm_x4(bm[0][g][0], bm[0][g][1], bm[0][g][2], bm[0][g][3],
                   st + OFF_B0 + b_off + g * 16 * PITCH);
            ldm_x4(bm[1][g][0], bm[1][g][1], bm[1][g][2], bm[1][g][3],
                   st + OFF_B1 + b_off + g * 16 * PITCH);
        }
#pragma unroll
        for (int z = 0; z < 2; z++)
#pragma unroll
            for (int m = 0; m < 2; m++)
#pragma unroll
                for (int n = 0; n < 4; n++)
                    mma_f16(acc[z][m][n], am[m], &bm[z][n >> 1][(n & 1) * 2]);
        __syncthreads();
    }

    // Epilogue: z=0 -> fp16 XL, z=1 -> fp16 XR
    const int cr = lane >> 2;               // 0..7
    const int cc = (lane & 3) * 2;
#pragma unroll
    for (int m = 0; m < 2; m++) {
#pragma unroll
        for (int half = 0; half < 2; half++) {
            const int gm = brow + warp_m + m * 16 + cr + half * 8;
            if (gm < NN) {
                __half* dst0 = g_XLh + (size_t)gm * DD + bn + warp_n + cc;
                __half* dst1 = g_XRh + (size_t)gm * DD + bn + warp_n + cc;
#pragma unroll
                for (int n = 0; n < 4; n++) {
                    *(__half2*)(dst0 + n * 8) = __floats2half2_rn(
                        acc[0][m][n][half * 2], acc[0][m][n][half * 2 + 1]);
                    *(__half2*)(dst1 + n * 8) = __floats2half2_rn(
                        acc[1][m][n][half * 2], acc[1][m][n][half * 2 + 1]);
                }
            }
        }
    }
}

// ---------------------------------------------------------------------------
// Fused gather + segment-softmax + weighted aggregate + ELU + residual.
// TWO warps per dst node; 8 channels per lane (head = 8-lane group).
// Half2 logit path (LeakyReLU(s) = 0.6s + 0.4|s|, exact), direct exp,
// fp32 accumulators, pre-multiplied byte offsets, pair prefetch (MLP 4).
// NEW: logit uses TWO independent half2 accumulators (p2a/p2b) to halve
// the serial HFMA2 dependency chain before the shfl reduction.
// ---------------------------------------------------------------------------
__global__ __launch_bounds__(256) void aggregate_kernel(const float* __restrict__ x,
                                                        const float* __restrict__ att,
                                                        const float* __restrict__ bias,
                                                        float* __restrict__ out) {
    const int gwarp = (blockIdx.x * blockDim.x + threadIdx.x) >> 5;  // 0..2*NN-1
    if (gwarp >= 2 * NN) return;
    const int gw = gwarp >> 1;                 // node
    const int lane = threadIdx.x & 31;
    const int bd = (gwarp & 1) * 256 + lane * 8;   // 8 channels; head = bd/64
    const int bdb = bd * 2;                        // byte offset within a row

    // Pre-scaled attention (half2) and xr (half2, loaded raw).
    __half2 a6[4], a4[4], xrh[4];
    {
        float4 t0 = *(const float4*)(att + bd);
        float4 t1 = *(const float4*)(att + bd + 4);
        a6[0] = __floats2half2_rn(0.6f * t0.x, 0.6f * t0.y);
        a6[1] = __floats2half2_rn(0.6f * t0.z, 0.6f * t0.w);
        a6[2] = __floats2half2_rn(0.6f * t1.x, 0.6f * t1.y);
        a6[3] = __floats2half2_rn(0.6f * t1.z, 0.6f * t1.w);
        a4[0] = __floats2half2_rn(0.4f * t0.x, 0.4f * t0.y);
        a4[1] = __floats2half2_rn(0.4f * t0.z, 0.4f * t0.w);
        a4[2] = __floats2half2_rn(0.4f * t1.x, 0.4f * t1.y);
        a4[3] = __floats2half2_rn(0.4f * t1.z, 0.4f * t1.w);
        uint4 u = *(const uint4*)((const char*)g_XRh + (size_t)gw * ROWB + bdb);
        xrh[0] = *(const __half2*)&u.x;
        xrh[1] = *(const __half2*)&u.y;
        xrh[2] = *(const __half2*)&u.z;
        xrh[3] = *(const __half2*)&u.w;
    }

    float acc[8];
#pragma unroll
    for (int t = 0; t < 8; t++) acc[t] = 0.f;
    float denom = 0.f;

    const int e0 = g_rowptr[gw];
    const int e1 = g_rowptr[gw + 1];   // e1 > e0 guaranteed (self loop)

    auto row_ptr = [&](int e) {
        return (const uint4*)((const char*)g_XLh + (size_t)(uint32_t)g_srcb[e] + bdb);
    };

    // softmax accumulation for one loaded row (1 uint4 = 4 half2 = 8 halves)
    auto process = [&](uint4 c) {
        __half2 xlh[4];
        xlh[0] = *(const __half2*)&c.x;
        xlh[1] = *(const __half2*)&c.y;
        xlh[2] = *(const __half2*)&c.z;
        xlh[3] = *(const __half2*)&c.w;

        // half2 logit, two independent chains: p += a6*(xl+xr) + a4*|xl+xr|
        __half2 p2a = __floats2half2_rn(0.f, 0.f);
        __half2 p2b = __floats2half2_rn(0.f, 0.f);
#pragma unroll
        for (int q = 0; q < 2; q++) {
            __half2 sa = __hadd2(xlh[q], xrh[q]);
            p2a = __hfma2(a6[q], sa, p2a);
            p2a = __hfma2(a4[q], __habs2(sa), p2a);
            __half2 sb = __hadd2(xlh[q + 2], xrh[q + 2]);
            p2b = __hfma2(a6[q + 2], sb, p2b);
            p2b = __hfma2(a4[q + 2], __habs2(sb), p2b);
        }
        float2 pf = __half22float2(__hadd2(p2a, p2b));
        float part = pf.x + pf.y;
        // reduce over the 8 lanes of this head (64 channels / 8 per lane)
        part += __shfl_xor_sync(0xffffffffu, part, 1);
        part += __shfl_xor_sync(0xffffffffu, part, 2);
        part += __shfl_xor_sync(0xffffffffu, part, 4);
        const float w = __expf(part);
        denom += w;
#pragma unroll
        for (int q = 0; q < 4; q++) {
            float2 f = __half22float2(xlh[q]);
            acc[2 * q]     = fmaf(w, f.x, acc[2 * q]);
            acc[2 * q + 1] = fmaf(w, f.y, acc[2 * q + 1]);
        }
    };

    int e = e0;
    int rem = e1 - e0;
    uint4 p0, p1;
    p0 = *row_ptr(e);
    if (rem > 1) p1 = *row_ptr(e + 1);
    while (rem >= 2) {
        const uint4 c0 = p0, c1 = p1;
        const int nx = e + 2;
        const int nrem = rem - 2;
        if (nrem > 0) {
            p0 = *row_ptr(nx);
            if (nrem > 1) p1 = *row_ptr(nx + 1);
        }
        process(c0);
        process(c1);
        e = nx;
        rem = nrem;
    }
    if (rem == 1) process(p0);

    const float inv = 1.0f / denom;
    const size_t ob = (size_t)gw * DD + bd;
#pragma unroll
    for (int q = 0; q < 2; q++) {
        float4 xv = *(const float4*)(x + ob + 4 * q);
        float r[4];
#pragma unroll
        for (int u = 0; u < 4; u++) {
            const int t = 4 * q + u;
            float v = acc[t] * inv + bias[bd + t];
            float e2 = (v > 0.f) ? v : expm1f(v);
            r[u] = e2 + ((const float*)&xv)[u];
        }
        *(float4*)(out + ob + 4 * q) = make_float4(r[0], r[1], r[2], r[3]);
    }
}

// ---------------------------------------------------------------------------
extern "C" void kernel_launch(void* const* d_in, const int* in_sizes, int n_in,
                              void* d_out, int out_size) {
    const float* x    = (const float*)d_in[0];
    const int*   ei   = (const int*)d_in[1];
    const float* W_l  = (const float*)d_in[2];
    const float* W_r  = (const float*)d_in[3];
    const float* att  = (const float*)d_in[4];
    const float* bias = (const float*)d_in[5];
    float* out = (float*)d_out;

    // 1) fused prep: x->fp16, W transpose->fp16, dst histogram
    prep_kernel<<<NB_PREP, 256>>>(x, W_l, W_r, ei);

    // 2) rowptr scan
    scan_kernel<<<1, 1024>>>();

    // 3) fused GEMM (R12 config: BN=64, 256 threads, 2-stage) + CSR scatter
    gemm_scatter_kernel<<<NB_GS, 256, 2 * STAGE>>>(ei);

    // 4) fused softmax-aggregate + ELU + residual (2 warps per node)
    aggregate_kernel<<<(2 * NN * 32 + 255) / 256, 256>>>(x, att, bias, out);
}